// round 3
// baseline (speedup 1.0000x reference)
#include <cuda_runtime.h>
#include <cuda_bf16.h>
#include <math.h>

#define Bq   8
#define Hq   32
#define KVH  8
#define HD   128
#define Dm   4096
#define Mlen 4096
#define NREP 4

#define KCH    16      // split-K depth (256 k per chunk)
#define KSTEP  256
#define NCHUNK 8
#define CHUNK  512

// ---------------- device scratch ----------------
__device__ __align__(16) float g_part1[KCH * Bq * 6144];
__device__ __align__(16) float g_qkv[Bq * 6144];
__device__ __align__(16) float g_pl[Bq * Hq * NCHUNK];
__device__ __align__(16) float g_pacc[Bq * Hq * NCHUNK * HD];
__device__ __align__(16) float g_attn[Bq * Dm];
__device__ __align__(16) float g_part2[KCH * Bq * Dm];

// -------- combined QKV split-K GEMM: part[kc][b][col], col in 0..6143 --------
__global__ void __launch_bounds__(128) gemm_qkv_part(
    const float* __restrict__ x,
    const float* __restrict__ wq, const float* __restrict__ wk,
    const float* __restrict__ wv, float* __restrict__ part)
{
    __shared__ float xs[Bq * KSTEP];
    const int tid = threadIdx.x;
    const int k0  = blockIdx.y * KSTEP;
    const int grp = blockIdx.x;          // 0..7 wq, 8..9 wk, 10..11 wv

    const float* w; int N, colg;
    if (grp < 8)       { w = wq; N = 4096; colg = grp * 512 + tid * 4; }
    else if (grp < 10) { w = wk; N = 1024; colg = 4096 + (grp - 8) * 512 + tid * 4; }
    else               { w = wv; N = 1024; colg = 5120 + (grp - 10) * 512 + tid * 4; }
    const int n = (grp < 8) ? (grp * 512 + tid * 4)
                            : (((grp - 8) & 1) * 512 + tid * 4);

    #pragma unroll
    for (int i = tid; i < Bq * KSTEP; i += 128) {
        int b = i >> 8, kk = i & (KSTEP - 1);
        xs[i] = x[b * Dm + k0 + kk];
    }
    __syncthreads();

    float4 acc[Bq];
    #pragma unroll
    for (int b = 0; b < Bq; b++) acc[b] = make_float4(0.f, 0.f, 0.f, 0.f);

    const float* wp = w + (size_t)k0 * N + n;
    #pragma unroll 8
    for (int kk = 0; kk < KSTEP; kk++) {
        float4 w4 = __ldcs((const float4*)(wp + (size_t)kk * N));
        #pragma unroll
        for (int b = 0; b < Bq; b++) {
            float xb = xs[b * KSTEP + kk];
            acc[b].x += xb * w4.x;
            acc[b].y += xb * w4.y;
            acc[b].z += xb * w4.z;
            acc[b].w += xb * w4.w;
        }
    }
    #pragma unroll
    for (int b = 0; b < Bq; b++)
        *(float4*)(part + ((size_t)(blockIdx.y * Bq + b)) * 6144 + colg) = acc[b];
}

// -------- plain split-K GEMM for wo: part[kc][b][n] --------
__global__ void __launch_bounds__(128) gemm_wo_part(
    const float* __restrict__ x, const float* __restrict__ w,
    float* __restrict__ part)
{
    __shared__ float xs[Bq * KSTEP];
    const int tid = threadIdx.x;
    const int k0  = blockIdx.y * KSTEP;
    const int n   = blockIdx.x * 512 + tid * 4;

    #pragma unroll
    for (int i = tid; i < Bq * KSTEP; i += 128) {
        int b = i >> 8, kk = i & (KSTEP - 1);
        xs[i] = x[b * Dm + k0 + kk];
    }
    __syncthreads();

    float4 acc[Bq];
    #pragma unroll
    for (int b = 0; b < Bq; b++) acc[b] = make_float4(0.f, 0.f, 0.f, 0.f);

    const float* wp = w + (size_t)k0 * 4096 + n;
    #pragma unroll 8
    for (int kk = 0; kk < KSTEP; kk++) {
        float4 w4 = __ldcs((const float4*)(wp + (size_t)kk * 4096));
        #pragma unroll
        for (int b = 0; b < Bq; b++) {
            float xb = xs[b * KSTEP + kk];
            acc[b].x += xb * w4.x;
            acc[b].y += xb * w4.y;
            acc[b].z += xb * w4.z;
            acc[b].w += xb * w4.w;
        }
    }
    #pragma unroll
    for (int b = 0; b < Bq; b++)
        *(float4*)(part + ((size_t)(blockIdx.y * Bq + b)) * Dm + n) = acc[b];
}

// ---------------- reduce partials + RoPE ----------------
__global__ void __launch_bounds__(256) rope_reduce(
    const float* __restrict__ part,
    const float* __restrict__ cosv, const float* __restrict__ sinv,
    float* __restrict__ qkv)
{
    int tid = blockIdx.x * blockDim.x + threadIdx.x;   // Bq*1536 float4s
    if (tid >= Bq * 1536) return;
    int b = tid / 1536;
    int col = (tid % 1536) * 4;

    float4 s = make_float4(0.f, 0.f, 0.f, 0.f);
    #pragma unroll
    for (int kc = 0; kc < KCH; kc++) {
        float4 v = *(const float4*)(part + ((size_t)(kc * Bq + b)) * 6144 + col);
        s.x += v.x; s.y += v.y; s.z += v.z; s.w += v.w;
    }
    if (col < 5120) {   // rope q and k
        int j0 = (col & 127) >> 1;
        float c0 = cosv[j0],     s0 = sinv[j0];
        float c1 = cosv[j0 + 1], s1 = sinv[j0 + 1];
        float o0 = s.x * c0 - s.y * s0;
        float o1 = s.x * s0 + s.y * c0;
        float o2 = s.z * c1 - s.w * s1;
        float o3 = s.z * s1 + s.w * c1;
        s = make_float4(o0, o1, o2, o3);
    }
    *(float4*)(qkv + b * 6144 + col) = s;
}

// ------------- fused: cache copy + flash-decode (half-warp rows) -------------
__global__ void __launch_bounds__(256) attn_fused(
    const float* __restrict__ ck, const float* __restrict__ cv,
    const float* __restrict__ qkv, const int* __restrict__ posp,
    float* __restrict__ out_ck, float* __restrict__ out_cv,
    float* __restrict__ pl, float* __restrict__ pacc, int write_cache)
{
    const int bx    = blockIdx.x;
    const int chunk = bx & (NCHUNK - 1);
    const int kv    = (bx >> 3) & (KVH - 1);
    const int b     = bx >> 6;
    const int tid   = threadIdx.x;
    const int lane  = tid & 31;
    const int warp  = tid >> 5;
    const int hw    = lane >> 4;
    const int j     = lane & 15;
    const int pos   = *posp;

    float4 q0[NREP], q1[NREP];
    #pragma unroll
    for (int r = 0; r < NREP; r++) {
        const float* qp = qkv + b * 6144 + (kv * NREP + r) * HD;
        q0[r] = *(const float4*)(qp + j * 4);
        q1[r] = *(const float4*)(qp + 64 + j * 4);
    }

    float4 acc0[NREP], acc1[NREP];
    float li[NREP];
    #pragma unroll
    for (int r = 0; r < NREP; r++) {
        acc0[r] = make_float4(0.f, 0.f, 0.f, 0.f);
        acc1[r] = make_float4(0.f, 0.f, 0.f, 0.f);
        li[r] = 0.f;
    }

    const float scale = 0.08838834764831845f;
    const size_t base = ((size_t)(b * KVH + kv)) * Mlen * HD;
    const float* newk = qkv + b * 6144 + 4096 + kv * HD;
    const float* newv = qkv + b * 6144 + 5120 + kv * HD;

    #pragma unroll 2
    for (int it = 0; it < CHUNK / 16; it++) {
        const int m = chunk * CHUNK + it * 16 + warp * 2 + hw;
        const size_t ro = base + (size_t)m * HD + j * 4;
        const bool sub = (m == pos);
        float4 k0, k1, v0, v1;
        if (sub) {
            k0 = *(const float4*)(newk + j * 4);
            k1 = *(const float4*)(newk + 64 + j * 4);
            v0 = *(const float4*)(newv + j * 4);
            v1 = *(const float4*)(newv + 64 + j * 4);
        } else {
            k0 = __ldcs((const float4*)(ck + ro));
            k1 = __ldcs((const float4*)(ck + ro + 64));
            v0 = __ldcs((const float4*)(cv + ro));
            v1 = __ldcs((const float4*)(cv + ro + 64));
        }
        if (write_cache) {
            __stcs((float4*)(out_ck + ro), k0);
            __stcs((float4*)(out_ck + ro + 64), k1);
            __stcs((float4*)(out_cv + ro), v0);
            __stcs((float4*)(out_cv + ro + 64), v1);
        }
        float s[NREP];
        #pragma unroll
        for (int r = 0; r < NREP; r++)
            s[r] = k0.x * q0[r].x + k0.y * q0[r].y + k0.z * q0[r].z + k0.w * q0[r].w
                 + k1.x * q1[r].x + k1.y * q1[r].y + k1.z * q1[r].z + k1.w * q1[r].w;
        #pragma unroll
        for (int off = 8; off; off >>= 1) {
            #pragma unroll
            for (int r = 0; r < NREP; r++)
                s[r] += __shfl_xor_sync(0xffffffff, s[r], off);
        }
        #pragma unroll
        for (int r = 0; r < NREP; r++) {
            float p = __expf(s[r] * scale);
            li[r] += p;
            acc0[r].x += p * v0.x; acc0[r].y += p * v0.y;
            acc0[r].z += p * v0.z; acc0[r].w += p * v0.w;
            acc1[r].x += p * v1.x; acc1[r].y += p * v1.y;
            acc1[r].z += p * v1.z; acc1[r].w += p * v1.w;
        }
    }

    #pragma unroll
    for (int r = 0; r < NREP; r++) {
        acc0[r].x += __shfl_xor_sync(0xffffffff, acc0[r].x, 16);
        acc0[r].y += __shfl_xor_sync(0xffffffff, acc0[r].y, 16);
        acc0[r].z += __shfl_xor_sync(0xffffffff, acc0[r].z, 16);
        acc0[r].w += __shfl_xor_sync(0xffffffff, acc0[r].w, 16);
        acc1[r].x += __shfl_xor_sync(0xffffffff, acc1[r].x, 16);
        acc1[r].y += __shfl_xor_sync(0xffffffff, acc1[r].y, 16);
        acc1[r].z += __shfl_xor_sync(0xffffffff, acc1[r].z, 16);
        acc1[r].w += __shfl_xor_sync(0xffffffff, acc1[r].w, 16);
        li[r] += __shfl_xor_sync(0xffffffff, li[r], 16);
    }

    __shared__ float sm_l[8][NREP];
    __shared__ __align__(16) float sm_acc[8][NREP][HD];
    if (hw == 0) {
        #pragma unroll
        for (int r = 0; r < NREP; r++) {
            *(float4*)&sm_acc[warp][r][j * 4]      = acc0[r];
            *(float4*)&sm_acc[warp][r][64 + j * 4] = acc1[r];
        }
        if (j == 0) {
            #pragma unroll
            for (int r = 0; r < NREP; r++) sm_l[warp][r] = li[r];
        }
    }
    __syncthreads();

    for (int idx = tid; idx < NREP * HD; idx += 256) {
        int r = idx >> 7, d = idx & (HD - 1);
        float L = 0.f, A = 0.f;
        #pragma unroll
        for (int w = 0; w < 8; w++) {
            L += sm_l[w][r];
            A += sm_acc[w][r][d];
        }
        int pidx = ((b * Hq + kv * NREP + r) * NCHUNK + chunk);
        pacc[(size_t)pidx * HD + d] = A;
        if (d == 0) pl[pidx] = L;
    }
}

// ---------------- combine chunk partials -> attn_out ----------------
__global__ void attn_reduce(const float* __restrict__ pl,
                            const float* __restrict__ pacc, float* __restrict__ attn)
{
    const int bh = blockIdx.x;
    const int d  = threadIdx.x;
    float L = 0.f, A = 0.f;
    #pragma unroll
    for (int c = 0; c < NCHUNK; c++) {
        L += pl[bh * NCHUNK + c];
        A += pacc[((size_t)bh * NCHUNK + c) * HD + d];
    }
    attn[bh * HD + d] = A / L;
}

// ---------------- combine wo partials -> final out ----------------
__global__ void __launch_bounds__(256) out_reduce(const float* __restrict__ part,
                                                  float* __restrict__ out)
{
    int tid = blockIdx.x * blockDim.x + threadIdx.x;  // Bq*1024 float4s
    if (tid >= Bq * 1024) return;
    int b = tid >> 10, n = (tid & 1023) * 4;
    float4 s = make_float4(0.f, 0.f, 0.f, 0.f);
    #pragma unroll
    for (int kc = 0; kc < KCH; kc++) {
        float4 v = *(const float4*)(part + ((size_t)(kc * Bq + b)) * Dm + n);
        s.x += v.x; s.y += v.y; s.z += v.z; s.w += v.w;
    }
    *(float4*)(out + b * Dm + n) = s;
}

// -------------------------------- host --------------------------------
extern "C" void kernel_launch(void* const* d_in, const int* in_sizes, int n_in,
                              void* d_out, int out_size)
{
    const float* x    = (const float*)d_in[0];
    const float* fcos = (const float*)d_in[1];
    const float* fsin = (const float*)d_in[2];
    const float* ck   = (const float*)d_in[4];
    const float* cv   = (const float*)d_in[5];
    const int* posp   = (n_in >= 13) ? (const int*)d_in[7] : (const int*)d_in[6];
    const float* wq   = (const float*)d_in[n_in - 4];
    const float* wk   = (const float*)d_in[n_in - 3];
    const float* wv   = (const float*)d_in[n_in - 2];
    const float* wo   = (const float*)d_in[n_in - 1];

    float *p1, *qkvp, *pl, *pacc, *attnp, *p2;
    { void* t; cudaGetSymbolAddress(&t, g_part1); p1    = (float*)t; }
    { void* t; cudaGetSymbolAddress(&t, g_qkv);   qkvp  = (float*)t; }
    { void* t; cudaGetSymbolAddress(&t, g_pl);    pl    = (float*)t; }
    { void* t; cudaGetSymbolAddress(&t, g_pacc);  pacc  = (float*)t; }
    { void* t; cudaGetSymbolAddress(&t, g_attn);  attnp = (float*)t; }
    { void* t; cudaGetSymbolAddress(&t, g_part2); p2    = (float*)t; }

    const long long need = 32768LL + 2LL * (long long)Bq * KVH * Mlen * HD;
    const int write_cache = ((long long)out_size >= need) ? 1 : 0;
    float* out   = (float*)d_out;
    float* outck = out + 32768;
    float* outcv = outck + (size_t)Bq * KVH * Mlen * HD;

    gemm_qkv_part<<<dim3(12, KCH), 128>>>(x, wq, wk, wv, p1);
    rope_reduce<<<48, 256>>>(p1, fcos, fsin, qkvp);
    attn_fused<<<Bq * KVH * NCHUNK, 256>>>(ck, cv, qkvp, posp,
                                           outck, outcv, pl, pacc, write_cache);
    attn_reduce<<<Bq * Hq, HD>>>(pl, pacc, attnp);
    gemm_wo_part<<<dim3(8, KCH), 128>>>(attnp, wo, p2);
    out_reduce<<<32, 256>>>(p2, out);
}

// round 4
// speedup vs baseline: 1.3766x; 1.3766x over previous
#include <cuda_runtime.h>
#include <cuda_bf16.h>
#include <math.h>

#define Bq   8
#define Hq   32
#define KVH  8
#define HD   128
#define Dm   4096
#define Mlen 4096
#define NREP 4

#define KSTEP  128     // k per gemm block
#define KCHQ   32      // 32 * 128 = 4096
#define NCHUNK 8
#define CHUNK  512

// ---------------- device scratch ----------------
__device__ __align__(16) float g_qkv[Bq * 6144];   // atomically accumulated
__device__ __align__(16) float g_pl[Bq * Hq * NCHUNK];
__device__ __align__(16) float g_pacc[Bq * Hq * NCHUNK * HD];
__device__ __align__(16) float g_attn[Bq * Dm];

// -------- combined QKV split-K GEMM, atomic accumulate into qkv --------
__global__ void __launch_bounds__(128) gemm_qkv_atom(
    const float* __restrict__ x,
    const float* __restrict__ wq, const float* __restrict__ wk,
    const float* __restrict__ wv, float* __restrict__ qkv)
{
    __shared__ float xs[Bq * KSTEP];
    const int tid = threadIdx.x;
    const int k0  = blockIdx.y * KSTEP;
    const int grp = blockIdx.x;          // 0..7 wq, 8..9 wk, 10..11 wv

    const float* w; int N, colg, n;
    if (grp < 8)       { w = wq; N = 4096; n = grp * 512 + tid * 4;        colg = n; }
    else if (grp < 10) { w = wk; N = 1024; n = (grp - 8) * 512 + tid * 4;  colg = 4096 + n; }
    else               { w = wv; N = 1024; n = (grp - 10) * 512 + tid * 4; colg = 5120 + n; }

    #pragma unroll
    for (int i = tid; i < Bq * KSTEP; i += 128) {
        int b = i >> 7, kk = i & (KSTEP - 1);
        xs[i] = x[b * Dm + k0 + kk];
    }
    __syncthreads();

    float4 acc[Bq];
    #pragma unroll
    for (int b = 0; b < Bq; b++) acc[b] = make_float4(0.f, 0.f, 0.f, 0.f);

    const float* wp = w + (size_t)k0 * N + n;
    #pragma unroll 8
    for (int kk = 0; kk < KSTEP; kk++) {
        float4 w4 = __ldcs((const float4*)(wp + (size_t)kk * N));
        #pragma unroll
        for (int b = 0; b < Bq; b++) {
            float xb = xs[b * KSTEP + kk];
            acc[b].x += xb * w4.x;
            acc[b].y += xb * w4.y;
            acc[b].z += xb * w4.z;
            acc[b].w += xb * w4.w;
        }
    }
    #pragma unroll
    for (int b = 0; b < Bq; b++) {
        float* dst = qkv + b * 6144 + colg;
        atomicAdd(dst + 0, acc[b].x);
        atomicAdd(dst + 1, acc[b].y);
        atomicAdd(dst + 2, acc[b].z);
        atomicAdd(dst + 3, acc[b].w);
    }
}

// -------- wo split-K GEMM, atomic accumulate into out --------
__global__ void __launch_bounds__(128) gemm_wo_atom(
    const float* __restrict__ x, const float* __restrict__ w,
    float* __restrict__ out)
{
    __shared__ float xs[Bq * KSTEP];
    const int tid = threadIdx.x;
    const int k0  = blockIdx.y * KSTEP;
    const int n   = blockIdx.x * 512 + tid * 4;

    #pragma unroll
    for (int i = tid; i < Bq * KSTEP; i += 128) {
        int b = i >> 7, kk = i & (KSTEP - 1);
        xs[i] = x[b * Dm + k0 + kk];
    }
    __syncthreads();

    float4 acc[Bq];
    #pragma unroll
    for (int b = 0; b < Bq; b++) acc[b] = make_float4(0.f, 0.f, 0.f, 0.f);

    const float* wp = w + (size_t)k0 * 4096 + n;
    #pragma unroll 8
    for (int kk = 0; kk < KSTEP; kk++) {
        float4 w4 = __ldcs((const float4*)(wp + (size_t)kk * 4096));
        #pragma unroll
        for (int b = 0; b < Bq; b++) {
            float xb = xs[b * KSTEP + kk];
            acc[b].x += xb * w4.x;
            acc[b].y += xb * w4.y;
            acc[b].z += xb * w4.z;
            acc[b].w += xb * w4.w;
        }
    }
    #pragma unroll
    for (int b = 0; b < Bq; b++) {
        float* dst = out + b * Dm + n;
        atomicAdd(dst + 0, acc[b].x);
        atomicAdd(dst + 1, acc[b].y);
        atomicAdd(dst + 2, acc[b].z);
        atomicAdd(dst + 3, acc[b].w);
    }
}

// ---------------- in-place RoPE on q|k part of qkv ----------------
__global__ void __launch_bounds__(256) rope_apply(
    float* __restrict__ qkv,
    const float* __restrict__ cosv, const float* __restrict__ sinv)
{
    int tid = blockIdx.x * blockDim.x + threadIdx.x;  // Bq*2560 pairs
    if (tid >= Bq * 2560) return;
    int b = tid / 2560;
    int col = (tid % 2560) * 2;          // 0..5118 (q then k)
    int j = (col & 127) >> 1;
    float2 v = *(float2*)(qkv + b * 6144 + col);
    float cj = cosv[j], sj = sinv[j];
    float o0 = v.x * cj - v.y * sj;
    float o1 = v.x * sj + v.y * cj;
    *(float2*)(qkv + b * 6144 + col) = make_float2(o0, o1);
}

// ------------- fused: cache copy + flash-decode (half-warp rows) -------------
__global__ void __launch_bounds__(256) attn_fused(
    const float* __restrict__ ck, const float* __restrict__ cv,
    const float* __restrict__ qkv, const int* __restrict__ posp,
    float* __restrict__ out_ck, float* __restrict__ out_cv,
    float* __restrict__ pl, float* __restrict__ pacc, int write_cache)
{
    const int bx    = blockIdx.x;
    const int chunk = bx & (NCHUNK - 1);
    const int kv    = (bx >> 3) & (KVH - 1);
    const int b     = bx >> 6;
    const int tid   = threadIdx.x;
    const int lane  = tid & 31;
    const int warp  = tid >> 5;
    const int hw    = lane >> 4;
    const int j     = lane & 15;
    const int pos   = *posp;

    float4 q0[NREP], q1[NREP];
    #pragma unroll
    for (int r = 0; r < NREP; r++) {
        const float* qp = qkv + b * 6144 + (kv * NREP + r) * HD;
        q0[r] = *(const float4*)(qp + j * 4);
        q1[r] = *(const float4*)(qp + 64 + j * 4);
    }

    float4 acc0[NREP], acc1[NREP];
    float li[NREP];
    #pragma unroll
    for (int r = 0; r < NREP; r++) {
        acc0[r] = make_float4(0.f, 0.f, 0.f, 0.f);
        acc1[r] = make_float4(0.f, 0.f, 0.f, 0.f);
        li[r] = 0.f;
    }

    const float scale = 0.08838834764831845f;
    const size_t base = ((size_t)(b * KVH + kv)) * Mlen * HD;
    const float* newk = qkv + b * 6144 + 4096 + kv * HD;
    const float* newv = qkv + b * 6144 + 5120 + kv * HD;

    #pragma unroll 2
    for (int it = 0; it < CHUNK / 16; it++) {
        const int m = chunk * CHUNK + it * 16 + warp * 2 + hw;
        const size_t ro = base + (size_t)m * HD + j * 4;
        const bool sub = (m == pos);
        float4 k0, k1, v0, v1;
        if (sub) {
            k0 = *(const float4*)(newk + j * 4);
            k1 = *(const float4*)(newk + 64 + j * 4);
            v0 = *(const float4*)(newv + j * 4);
            v1 = *(const float4*)(newv + 64 + j * 4);
        } else {
            k0 = __ldcs((const float4*)(ck + ro));
            k1 = __ldcs((const float4*)(ck + ro + 64));
            v0 = __ldcs((const float4*)(cv + ro));
            v1 = __ldcs((const float4*)(cv + ro + 64));
        }
        if (write_cache) {
            __stcs((float4*)(out_ck + ro), k0);
            __stcs((float4*)(out_ck + ro + 64), k1);
            __stcs((float4*)(out_cv + ro), v0);
            __stcs((float4*)(out_cv + ro + 64), v1);
        }
        float s[NREP];
        #pragma unroll
        for (int r = 0; r < NREP; r++)
            s[r] = k0.x * q0[r].x + k0.y * q0[r].y + k0.z * q0[r].z + k0.w * q0[r].w
                 + k1.x * q1[r].x + k1.y * q1[r].y + k1.z * q1[r].z + k1.w * q1[r].w;
        #pragma unroll
        for (int off = 8; off; off >>= 1) {
            #pragma unroll
            for (int r = 0; r < NREP; r++)
                s[r] += __shfl_xor_sync(0xffffffff, s[r], off);
        }
        #pragma unroll
        for (int r = 0; r < NREP; r++) {
            float p = __expf(s[r] * scale);
            li[r] += p;
            acc0[r].x += p * v0.x; acc0[r].y += p * v0.y;
            acc0[r].z += p * v0.z; acc0[r].w += p * v0.w;
            acc1[r].x += p * v1.x; acc1[r].y += p * v1.y;
            acc1[r].z += p * v1.z; acc1[r].w += p * v1.w;
        }
    }

    #pragma unroll
    for (int r = 0; r < NREP; r++) {
        acc0[r].x += __shfl_xor_sync(0xffffffff, acc0[r].x, 16);
        acc0[r].y += __shfl_xor_sync(0xffffffff, acc0[r].y, 16);
        acc0[r].z += __shfl_xor_sync(0xffffffff, acc0[r].z, 16);
        acc0[r].w += __shfl_xor_sync(0xffffffff, acc0[r].w, 16);
        acc1[r].x += __shfl_xor_sync(0xffffffff, acc1[r].x, 16);
        acc1[r].y += __shfl_xor_sync(0xffffffff, acc1[r].y, 16);
        acc1[r].z += __shfl_xor_sync(0xffffffff, acc1[r].z, 16);
        acc1[r].w += __shfl_xor_sync(0xffffffff, acc1[r].w, 16);
        li[r] += __shfl_xor_sync(0xffffffff, li[r], 16);
    }

    __shared__ float sm_l[8][NREP];
    __shared__ __align__(16) float sm_acc[8][NREP][HD];
    if (hw == 0) {
        #pragma unroll
        for (int r = 0; r < NREP; r++) {
            *(float4*)&sm_acc[warp][r][j * 4]      = acc0[r];
            *(float4*)&sm_acc[warp][r][64 + j * 4] = acc1[r];
        }
        if (j == 0) {
            #pragma unroll
            for (int r = 0; r < NREP; r++) sm_l[warp][r] = li[r];
        }
    }
    __syncthreads();

    for (int idx = tid; idx < NREP * HD; idx += 256) {
        int r = idx >> 7, d = idx & (HD - 1);
        float L = 0.f, A = 0.f;
        #pragma unroll
        for (int w = 0; w < 8; w++) {
            L += sm_l[w][r];
            A += sm_acc[w][r][d];
        }
        int pidx = ((b * Hq + kv * NREP + r) * NCHUNK + chunk);
        pacc[(size_t)pidx * HD + d] = A;
        if (d == 0) pl[pidx] = L;
    }
}

// ---------------- combine chunk partials -> attn_out (1 warp / bh) ----------------
__global__ void __launch_bounds__(32) attn_reduce(
    const float* __restrict__ pl, const float* __restrict__ pacc,
    float* __restrict__ attn)
{
    const int bh   = blockIdx.x;
    const int lane = threadIdx.x;
    float L = 0.f;
    float4 A = make_float4(0.f, 0.f, 0.f, 0.f);
    #pragma unroll
    for (int c = 0; c < NCHUNK; c++) {
        L += pl[bh * NCHUNK + c];
        float4 v = *(const float4*)(pacc + ((size_t)bh * NCHUNK + c) * HD + lane * 4);
        A.x += v.x; A.y += v.y; A.z += v.z; A.w += v.w;
    }
    float inv = 1.0f / L;
    *(float4*)(attn + bh * HD + lane * 4) =
        make_float4(A.x * inv, A.y * inv, A.z * inv, A.w * inv);
}

// -------------------------------- host --------------------------------
extern "C" void kernel_launch(void* const* d_in, const int* in_sizes, int n_in,
                              void* d_out, int out_size)
{
    const float* x    = (const float*)d_in[0];
    const float* fcos = (const float*)d_in[1];
    const float* fsin = (const float*)d_in[2];
    const float* ck   = (const float*)d_in[4];
    const float* cv   = (const float*)d_in[5];
    const int* posp   = (n_in >= 13) ? (const int*)d_in[7] : (const int*)d_in[6];
    const float* wq   = (const float*)d_in[n_in - 4];
    const float* wk   = (const float*)d_in[n_in - 3];
    const float* wv   = (const float*)d_in[n_in - 2];
    const float* wo   = (const float*)d_in[n_in - 1];

    float *qkvp, *pl, *pacc, *attnp;
    { void* t; cudaGetSymbolAddress(&t, g_qkv);  qkvp  = (float*)t; }
    { void* t; cudaGetSymbolAddress(&t, g_pl);   pl    = (float*)t; }
    { void* t; cudaGetSymbolAddress(&t, g_pacc); pacc  = (float*)t; }
    { void* t; cudaGetSymbolAddress(&t, g_attn); attnp = (float*)t; }

    const long long need = 32768LL + 2LL * (long long)Bq * KVH * Mlen * HD;
    const int write_cache = ((long long)out_size >= need) ? 1 : 0;
    float* out   = (float*)d_out;
    float* outck = out + 32768;
    float* outcv = outck + (size_t)Bq * KVH * Mlen * HD;

    // zero the atomic accumulators (graph-capturable async memsets)
    cudaMemsetAsync(qkvp, 0, Bq * 6144 * sizeof(float));
    cudaMemsetAsync(out, 0, Bq * Dm * sizeof(float));

    // 1) QKV projection (split-K, atomic accumulate) — 384 blocks
    gemm_qkv_atom<<<dim3(12, KCHQ), 128>>>(x, wq, wk, wv, qkvp);
    // 2) in-place RoPE on q|k
    rope_apply<<<80, 256>>>(qkvp, fcos, fsin);
    // 3) fused cache copy + flash-decode partials
    attn_fused<<<Bq * KVH * NCHUNK, 256>>>(ck, cv, qkvp, posp,
                                           outck, outcv, pl, pacc, write_cache);
    // 4) softmax combine
    attn_reduce<<<Bq * Hq, 32>>>(pl, pacc, attnp);
    // 5) output projection (split-K, atomic accumulate) — 256 blocks
    gemm_wo_atom<<<dim3(8, KCHQ), 128>>>(attnp, wo, out);
}

// round 5
// speedup vs baseline: 1.4683x; 1.0666x over previous
#include <cuda_runtime.h>
#include <cuda_bf16.h>
#include <math.h>

#define Bq   8
#define Hq   32
#define KVH  8
#define HD   128
#define Dm   4096
#define Mlen 4096
#define NREP 4

#define KSTEP  64      // k per gemm block
#define KCH    64      // 64 * 64 = 4096
#define NCHUNK 8
#define CHUNK  512

// ---------------- device scratch ----------------
__device__ __align__(16) float g_qkv[Bq * 6144];   // atomically accumulated (raw, un-roped)
__device__ __align__(16) float g_pl[Bq * Hq * NCHUNK];
__device__ __align__(16) float g_pacc[Bq * Hq * NCHUNK * HD];
__device__ __align__(16) float g_attn[Bq * Dm];

// -------- combined QKV split-K GEMM, atomic accumulate into qkv --------
__global__ void __launch_bounds__(128) gemm_qkv_atom(
    const float* __restrict__ x,
    const float* __restrict__ wq, const float* __restrict__ wk,
    const float* __restrict__ wv, float* __restrict__ qkv)
{
    __shared__ __align__(16) float4 xs[KSTEP][2];   // [k][b-quad]
    const int tid = threadIdx.x;
    const int k0  = blockIdx.y * KSTEP;
    const int grp = blockIdx.x;          // 0..7 wq, 8..9 wk, 10..11 wv

    const float* w; int N, colg, n;
    if (grp < 8)       { w = wq; N = 4096; n = grp * 512 + tid * 4;        colg = n; }
    else if (grp < 10) { w = wk; N = 1024; n = (grp - 8) * 512 + tid * 4;  colg = 4096 + n; }
    else               { w = wv; N = 1024; n = (grp - 10) * 512 + tid * 4; colg = 5120 + n; }

    for (int i = tid; i < KSTEP * 2; i += 128) {
        int kk = i >> 1, h = (i & 1) * 4;
        xs[kk][i & 1] = make_float4(x[(h + 0) * Dm + k0 + kk], x[(h + 1) * Dm + k0 + kk],
                                    x[(h + 2) * Dm + k0 + kk], x[(h + 3) * Dm + k0 + kk]);
    }
    __syncthreads();

    float4 acc[Bq];
    #pragma unroll
    for (int b = 0; b < Bq; b++) acc[b] = make_float4(0.f, 0.f, 0.f, 0.f);

    const float* wp = w + (size_t)k0 * N + n;
    #pragma unroll 8
    for (int kk = 0; kk < KSTEP; kk++) {
        float4 w4 = __ldcs((const float4*)(wp + (size_t)kk * N));
        float4 xa = xs[kk][0], xb = xs[kk][1];
        acc[0].x += xa.x * w4.x; acc[0].y += xa.x * w4.y; acc[0].z += xa.x * w4.z; acc[0].w += xa.x * w4.w;
        acc[1].x += xa.y * w4.x; acc[1].y += xa.y * w4.y; acc[1].z += xa.y * w4.z; acc[1].w += xa.y * w4.w;
        acc[2].x += xa.z * w4.x; acc[2].y += xa.z * w4.y; acc[2].z += xa.z * w4.z; acc[2].w += xa.z * w4.w;
        acc[3].x += xa.w * w4.x; acc[3].y += xa.w * w4.y; acc[3].z += xa.w * w4.z; acc[3].w += xa.w * w4.w;
        acc[4].x += xb.x * w4.x; acc[4].y += xb.x * w4.y; acc[4].z += xb.x * w4.z; acc[4].w += xb.x * w4.w;
        acc[5].x += xb.y * w4.x; acc[5].y += xb.y * w4.y; acc[5].z += xb.y * w4.z; acc[5].w += xb.y * w4.w;
        acc[6].x += xb.z * w4.x; acc[6].y += xb.z * w4.y; acc[6].z += xb.z * w4.z; acc[6].w += xb.z * w4.w;
        acc[7].x += xb.w * w4.x; acc[7].y += xb.w * w4.y; acc[7].z += xb.w * w4.z; acc[7].w += xb.w * w4.w;
    }
    #pragma unroll
    for (int b = 0; b < Bq; b++) {
        float* dst = qkv + b * 6144 + colg;
        atomicAdd(dst + 0, acc[b].x);
        atomicAdd(dst + 1, acc[b].y);
        atomicAdd(dst + 2, acc[b].z);
        atomicAdd(dst + 3, acc[b].w);
    }
}

// -------- wo split-K GEMM, atomic accumulate into out --------
__global__ void __launch_bounds__(128) gemm_wo_atom(
    const float* __restrict__ x, const float* __restrict__ w,
    float* __restrict__ out)
{
    __shared__ __align__(16) float4 xs[KSTEP][2];
    const int tid = threadIdx.x;
    const int k0  = blockIdx.y * KSTEP;
    const int n   = blockIdx.x * 512 + tid * 4;

    for (int i = tid; i < KSTEP * 2; i += 128) {
        int kk = i >> 1, h = (i & 1) * 4;
        xs[kk][i & 1] = make_float4(x[(h + 0) * Dm + k0 + kk], x[(h + 1) * Dm + k0 + kk],
                                    x[(h + 2) * Dm + k0 + kk], x[(h + 3) * Dm + k0 + kk]);
    }
    __syncthreads();

    float4 acc[Bq];
    #pragma unroll
    for (int b = 0; b < Bq; b++) acc[b] = make_float4(0.f, 0.f, 0.f, 0.f);

    const float* wp = w + (size_t)k0 * 4096 + n;
    #pragma unroll 8
    for (int kk = 0; kk < KSTEP; kk++) {
        float4 w4 = __ldcs((const float4*)(wp + (size_t)kk * 4096));
        float4 xa = xs[kk][0], xb = xs[kk][1];
        acc[0].x += xa.x * w4.x; acc[0].y += xa.x * w4.y; acc[0].z += xa.x * w4.z; acc[0].w += xa.x * w4.w;
        acc[1].x += xa.y * w4.x; acc[1].y += xa.y * w4.y; acc[1].z += xa.y * w4.z; acc[1].w += xa.y * w4.w;
        acc[2].x += xa.z * w4.x; acc[2].y += xa.z * w4.y; acc[2].z += xa.z * w4.z; acc[2].w += xa.z * w4.w;
        acc[3].x += xa.w * w4.x; acc[3].y += xa.w * w4.y; acc[3].z += xa.w * w4.z; acc[3].w += xa.w * w4.w;
        acc[4].x += xb.x * w4.x; acc[4].y += xb.x * w4.y; acc[4].z += xb.x * w4.z; acc[4].w += xb.x * w4.w;
        acc[5].x += xb.y * w4.x; acc[5].y += xb.y * w4.y; acc[5].z += xb.y * w4.z; acc[5].w += xb.y * w4.w;
        acc[6].x += xb.z * w4.x; acc[6].y += xb.z * w4.y; acc[6].z += xb.z * w4.z; acc[6].w += xb.z * w4.w;
        acc[7].x += xb.w * w4.x; acc[7].y += xb.w * w4.y; acc[7].z += xb.w * w4.z; acc[7].w += xb.w * w4.w;
    }
    #pragma unroll
    for (int b = 0; b < Bq; b++) {
        float* dst = out + b * Dm + n;
        atomicAdd(dst + 0, acc[b].x);
        atomicAdd(dst + 1, acc[b].y);
        atomicAdd(dst + 2, acc[b].z);
        atomicAdd(dst + 3, acc[b].w);
    }
}

// rope a float4 covering dims 4j..4j+3 (pairs 2j, 2j+1), cos/sin base index cj0
__device__ __forceinline__ float4 rope4(float4 v, const float* cosv, const float* sinv, int cj0)
{
    float c0 = cosv[cj0], s0 = sinv[cj0];
    float c1 = cosv[cj0 + 1], s1 = sinv[cj0 + 1];
    return make_float4(v.x * c0 - v.y * s0, v.x * s0 + v.y * c0,
                       v.z * c1 - v.w * s1, v.z * s1 + v.w * c1);
}

// ------------- fused: RoPE + cache copy + flash-decode (half-warp rows) -------------
__global__ void __launch_bounds__(256) attn_fused(
    const float* __restrict__ ck, const float* __restrict__ cv,
    const float* __restrict__ qkv, const int* __restrict__ posp,
    const float* __restrict__ cosv, const float* __restrict__ sinv,
    float* __restrict__ out_ck, float* __restrict__ out_cv,
    float* __restrict__ pl, float* __restrict__ pacc, int write_cache)
{
    const int bx    = blockIdx.x;
    const int chunk = bx & (NCHUNK - 1);
    const int kv    = (bx >> 3) & (KVH - 1);
    const int b     = bx >> 6;
    const int tid   = threadIdx.x;
    const int lane  = tid & 31;
    const int warp  = tid >> 5;
    const int hw    = lane >> 4;
    const int j     = lane & 15;
    const int pos   = *posp;

    // q: rope applied in-register (raw qkv buffer)
    float4 q0[NREP], q1[NREP];
    #pragma unroll
    for (int r = 0; r < NREP; r++) {
        const float* qp = qkv + b * 6144 + (kv * NREP + r) * HD;
        q0[r] = rope4(*(const float4*)(qp + j * 4),      cosv, sinv, 2 * j);
        q1[r] = rope4(*(const float4*)(qp + 64 + j * 4), cosv, sinv, 32 + 2 * j);
    }
    // new k (roped) and v rows for the pos substitution
    const float* nkp = qkv + b * 6144 + 4096 + kv * HD;
    const float* nvp = qkv + b * 6144 + 5120 + kv * HD;
    float4 nk0 = rope4(*(const float4*)(nkp + j * 4),      cosv, sinv, 2 * j);
    float4 nk1 = rope4(*(const float4*)(nkp + 64 + j * 4), cosv, sinv, 32 + 2 * j);
    float4 nv0 = *(const float4*)(nvp + j * 4);
    float4 nv1 = *(const float4*)(nvp + 64 + j * 4);

    float4 acc0[NREP], acc1[NREP];
    float li[NREP];
    #pragma unroll
    for (int r = 0; r < NREP; r++) {
        acc0[r] = make_float4(0.f, 0.f, 0.f, 0.f);
        acc1[r] = make_float4(0.f, 0.f, 0.f, 0.f);
        li[r] = 0.f;
    }

    const float scale = 0.08838834764831845f;
    const size_t base = ((size_t)(b * KVH + kv)) * Mlen * HD;

    #pragma unroll 2
    for (int it = 0; it < CHUNK / 16; it++) {
        const int m = chunk * CHUNK + it * 16 + warp * 2 + hw;
        const size_t ro = base + (size_t)m * HD + j * 4;
        const bool sub = (m == pos);
        float4 k0, k1, v0, v1;
        if (sub) {
            k0 = nk0; k1 = nk1; v0 = nv0; v1 = nv1;
        } else {
            k0 = __ldcs((const float4*)(ck + ro));
            k1 = __ldcs((const float4*)(ck + ro + 64));
            v0 = __ldcs((const float4*)(cv + ro));
            v1 = __ldcs((const float4*)(cv + ro + 64));
        }
        if (write_cache) {
            __stcs((float4*)(out_ck + ro), k0);
            __stcs((float4*)(out_ck + ro + 64), k1);
            __stcs((float4*)(out_cv + ro), v0);
            __stcs((float4*)(out_cv + ro + 64), v1);
        }
        float s[NREP];
        #pragma unroll
        for (int r = 0; r < NREP; r++)
            s[r] = k0.x * q0[r].x + k0.y * q0[r].y + k0.z * q0[r].z + k0.w * q0[r].w
                 + k1.x * q1[r].x + k1.y * q1[r].y + k1.z * q1[r].z + k1.w * q1[r].w;
        #pragma unroll
        for (int off = 8; off; off >>= 1) {
            #pragma unroll
            for (int r = 0; r < NREP; r++)
                s[r] += __shfl_xor_sync(0xffffffff, s[r], off);
        }
        #pragma unroll
        for (int r = 0; r < NREP; r++) {
            float p = __expf(s[r] * scale);
            li[r] += p;
            acc0[r].x += p * v0.x; acc0[r].y += p * v0.y;
            acc0[r].z += p * v0.z; acc0[r].w += p * v0.w;
            acc1[r].x += p * v1.x; acc1[r].y += p * v1.y;
            acc1[r].z += p * v1.z; acc1[r].w += p * v1.w;
        }
    }

    #pragma unroll
    for (int r = 0; r < NREP; r++) {
        acc0[r].x += __shfl_xor_sync(0xffffffff, acc0[r].x, 16);
        acc0[r].y += __shfl_xor_sync(0xffffffff, acc0[r].y, 16);
        acc0[r].z += __shfl_xor_sync(0xffffffff, acc0[r].z, 16);
        acc0[r].w += __shfl_xor_sync(0xffffffff, acc0[r].w, 16);
        acc1[r].x += __shfl_xor_sync(0xffffffff, acc1[r].x, 16);
        acc1[r].y += __shfl_xor_sync(0xffffffff, acc1[r].y, 16);
        acc1[r].z += __shfl_xor_sync(0xffffffff, acc1[r].z, 16);
        acc1[r].w += __shfl_xor_sync(0xffffffff, acc1[r].w, 16);
        li[r] += __shfl_xor_sync(0xffffffff, li[r], 16);
    }

    __shared__ float sm_l[8][NREP];
    __shared__ __align__(16) float sm_acc[8][NREP][HD];
    if (hw == 0) {
        #pragma unroll
        for (int r = 0; r < NREP; r++) {
            *(float4*)&sm_acc[warp][r][j * 4]      = acc0[r];
            *(float4*)&sm_acc[warp][r][64 + j * 4] = acc1[r];
        }
        if (j == 0) {
            #pragma unroll
            for (int r = 0; r < NREP; r++) sm_l[warp][r] = li[r];
        }
    }
    __syncthreads();

    for (int idx = tid; idx < NREP * HD; idx += 256) {
        int r = idx >> 7, d = idx & (HD - 1);
        float L = 0.f, A = 0.f;
        #pragma unroll
        for (int w = 0; w < 8; w++) {
            L += sm_l[w][r];
            A += sm_acc[w][r][d];
        }
        int pidx = ((b * Hq + kv * NREP + r) * NCHUNK + chunk);
        pacc[(size_t)pidx * HD + d] = A;
        if (d == 0) pl[pidx] = L;
    }
}

// ---------------- combine chunk partials -> attn_out (1 warp / bh) ----------------
__global__ void __launch_bounds__(32) attn_reduce(
    const float* __restrict__ pl, const float* __restrict__ pacc,
    float* __restrict__ attn)
{
    const int bh   = blockIdx.x;
    const int lane = threadIdx.x;
    float L = 0.f;
    float4 A = make_float4(0.f, 0.f, 0.f, 0.f);
    #pragma unroll
    for (int c = 0; c < NCHUNK; c++) {
        L += pl[bh * NCHUNK + c];
        float4 v = *(const float4*)(pacc + ((size_t)bh * NCHUNK + c) * HD + lane * 4);
        A.x += v.x; A.y += v.y; A.z += v.z; A.w += v.w;
    }
    float inv = 1.0f / L;
    *(float4*)(attn + bh * HD + lane * 4) =
        make_float4(A.x * inv, A.y * inv, A.z * inv, A.w * inv);
}

// -------------------------------- host --------------------------------
extern "C" void kernel_launch(void* const* d_in, const int* in_sizes, int n_in,
                              void* d_out, int out_size)
{
    const float* x    = (const float*)d_in[0];
    const float* fcos = (const float*)d_in[1];
    const float* fsin = (const float*)d_in[2];
    const float* ck   = (const float*)d_in[4];
    const float* cv   = (const float*)d_in[5];
    const int* posp   = (n_in >= 13) ? (const int*)d_in[7] : (const int*)d_in[6];
    const float* wq   = (const float*)d_in[n_in - 4];
    const float* wk   = (const float*)d_in[n_in - 3];
    const float* wv   = (const float*)d_in[n_in - 2];
    const float* wo   = (const float*)d_in[n_in - 1];

    float *qkvp, *pl, *pacc, *attnp;
    { void* t; cudaGetSymbolAddress(&t, g_qkv);  qkvp  = (float*)t; }
    { void* t; cudaGetSymbolAddress(&t, g_pl);   pl    = (float*)t; }
    { void* t; cudaGetSymbolAddress(&t, g_pacc); pacc  = (float*)t; }
    { void* t; cudaGetSymbolAddress(&t, g_attn); attnp = (float*)t; }

    const long long need = 32768LL + 2LL * (long long)Bq * KVH * Mlen * HD;
    const int write_cache = ((long long)out_size >= need) ? 1 : 0;
    float* out   = (float*)d_out;
    float* outck = out + 32768;
    float* outcv = outck + (size_t)Bq * KVH * Mlen * HD;

    cudaMemsetAsync(qkvp, 0, Bq * 6144 * sizeof(float));
    cudaMemsetAsync(out, 0, Bq * Dm * sizeof(float));

    // 1) QKV projection (split-K x64, atomic accumulate) — 768 blocks
    gemm_qkv_atom<<<dim3(12, KCH), 128>>>(x, wq, wk, wv, qkvp);
    // 2) fused RoPE + cache copy + flash-decode partials
    attn_fused<<<Bq * KVH * NCHUNK, 256>>>(ck, cv, qkvp, posp, fcos, fsin,
                                           outck, outcv, pl, pacc, write_cache);
    // 3) softmax combine
    attn_reduce<<<Bq * Hq, 32>>>(pl, pacc, attnp);
    // 4) output projection (split-K x64, atomic accumulate) — 512 blocks
    gemm_wo_atom<<<dim3(8, KCH), 128>>>(attnp, wo, out);
}